// round 1
// baseline (speedup 1.0000x reference)
#include <cuda_runtime.h>
#include <cuda_bf16.h>

// ---------------------------------------------------------------------------
// GNN15: two GAT branches (int: 400K edges, nh: 1.6M edges) over 100K nodes,
// HEADS=3, FILT=16, then global attention pooling to a scalar.
// ---------------------------------------------------------------------------

#define NN      100000
#define E_INT   400000
#define E_NH    1600000
#define VF      11
#define HEADS   3
#define HF      48      // HEADS*FILT
#define XDIM    96      // 2*HF

// ---------------- scratch (static device globals; no allocation) -----------
__device__ __align__(16) float g_h0[NN * HF];     // h for branch int
__device__ __align__(16) float g_h1[NN * HF];     // h for branch nh
__device__ float g_es0[NN * HEADS];
__device__ float g_ed0[NN * HEADS];
__device__ float g_es1[NN * HEADS];
__device__ float g_ed1[NN * HEADS];
__device__ float g_den0[NN * HEADS];
__device__ float g_den1[NN * HEADS];
__device__ __align__(16) float g_out0[NN * HF];
__device__ __align__(16) float g_out1[NN * HF];
__device__ float g_p[E_NH * HEADS];               // reused across branches (sequential)
__device__ float g_acc[8];                        // num[3], den[3]
__device__ int   g_is64[2];                       // edge dtype flags (0: int, 1: nh)

// ---------------- dtype detection + tiny init ------------------------------
// jax "int64" edges are int32 unless x64 is enabled. Values < 1e5 << 2^31,
// so if truly int64, every odd int32 word is 0. Check 16 of them.
__global__ void detect_kernel(const void* e0, const void* e1) {
    const int* a = (const int*)e0;
    const int* b = (const int*)e1;
    int is64a = 1, is64b = 1;
    #pragma unroll
    for (int i = 0; i < 16; i++) {
        if (a[2 * i + 1] != 0) is64a = 0;
        if (b[2 * i + 1] != 0) is64b = 0;
    }
    g_is64[0] = is64a;
    g_is64[1] = is64b;
    #pragma unroll
    for (int i = 0; i < 8; i++) g_acc[i] = 0.0f;
}

__global__ void zero_kernel(float* p, int n) {
    int i = blockIdx.x * blockDim.x + threadIdx.x;
    if (i < n) p[i] = 0.0f;
}

// ---------------- node transform: h = x@W, es/ed scores, both branches -----
__global__ void node_kernel(const float* __restrict__ feats,
                            const float* __restrict__ W0,
                            const float* __restrict__ as0, const float* __restrict__ ad0,
                            const float* __restrict__ W1,
                            const float* __restrict__ as1, const float* __restrict__ ad1) {
    __shared__ float sW[2][VF * HF];     // [11][48] each
    __shared__ float sAs[2][HF];
    __shared__ float sAd[2][HF];
    int tid = threadIdx.x;
    for (int i = tid; i < VF * HF; i += blockDim.x) { sW[0][i] = W0[i]; sW[1][i] = W1[i]; }
    for (int i = tid; i < HF; i += blockDim.x) {
        sAs[0][i] = as0[i]; sAd[0][i] = ad0[i];
        sAs[1][i] = as1[i]; sAd[1][i] = ad1[i];
    }
    __syncthreads();

    int n = blockIdx.x * blockDim.x + tid;
    if (n >= NN) return;

    float x[VF];
    #pragma unroll
    for (int k = 0; k < VF; k++) x[k] = feats[(size_t)n * VF + k];

    #pragma unroll
    for (int b = 0; b < 2; b++) {
        float* hout = (b == 0 ? g_h0 : g_h1) + (size_t)n * HF;
        float es[HEADS] = {0.f, 0.f, 0.f};
        float ed[HEADS] = {0.f, 0.f, 0.f};
        #pragma unroll
        for (int j = 0; j < HF; j++) {
            float s = 0.f;
            #pragma unroll
            for (int k = 0; k < VF; k++) s += x[k] * sW[b][k * HF + j];
            hout[j] = s;
            int hh = j >> 4;
            es[hh] += s * sAs[b][j];
            ed[hh] += s * sAd[b][j];
        }
        float* pes = (b == 0 ? g_es0 : g_es1) + (size_t)n * HEADS;
        float* ped = (b == 0 ? g_ed0 : g_ed1) + (size_t)n * HEADS;
        #pragma unroll
        for (int hh = 0; hh < HEADS; hh++) { pes[hh] = es[hh]; ped[hh] = ed[hh]; }
    }
}

// ---------------- edge pass 1: p = exp(lrelu(es[src]+ed[dst])), denom +=  --
__global__ void edge_pass1(const void* __restrict__ edges, int E, int which,
                           const float* __restrict__ es, const float* __restrict__ ed,
                           float* __restrict__ den, float* __restrict__ pbuf) {
    int e = blockIdx.x * blockDim.x + threadIdx.x;
    if (e >= E) return;
    int s, d;
    if (g_is64[which]) {
        const long long* E64 = (const long long*)edges;
        s = (int)E64[e]; d = (int)E64[E + e];
    } else {
        const int* E32 = (const int*)edges;
        s = E32[e]; d = E32[E + e];
    }
    #pragma unroll
    for (int h = 0; h < HEADS; h++) {
        float v = es[s * HEADS + h] + ed[d * HEADS + h];
        v = v > 0.f ? v : 0.2f * v;                 // leaky_relu(0.2)
        float p = __expf(v);                        // no max-shift needed (|v| small)
        pbuf[(size_t)e * HEADS + h] = p;
        atomicAdd(&den[d * HEADS + h], p);
    }
}

// ---------------- edge pass 2: out[dst] += alpha * h[src] (4 thr/edge) -----
__global__ void edge_pass2(const void* __restrict__ edges, int E, int which,
                           const float* __restrict__ hsrc,
                           const float* __restrict__ den,
                           const float* __restrict__ pbuf,
                           float* __restrict__ out) {
    int t = blockIdx.x * blockDim.x + threadIdx.x;
    int e = t >> 2;
    int lane = t & 3;
    if (e >= E) return;
    int s, d;
    if (g_is64[which]) {
        const long long* E64 = (const long long*)edges;
        s = (int)E64[e]; d = (int)E64[E + e];
    } else {
        const int* E32 = (const int*)edges;
        s = E32[e]; d = E32[E + e];
    }
    float alpha[HEADS];
    #pragma unroll
    for (int k = 0; k < HEADS; k++)
        alpha[k] = pbuf[(size_t)e * HEADS + k] / (den[d * HEADS + k] + 1e-16f);

    const float4* hs = (const float4*)(hsrc + (size_t)s * HF);
    float* ob = out + (size_t)d * HF;
    #pragma unroll
    for (int k = 0; k < HEADS; k++) {
        float4 v = hs[lane + 4 * k];
        float a = alpha[k];
        v.x *= a; v.y *= a; v.z *= a; v.w *= a;
        float* addr = ob + (size_t)(lane + 4 * k) * 4;
        asm volatile("red.global.add.v4.f32 [%0], {%1,%2,%3,%4};"
                     :: "l"(addr), "f"(v.x), "f"(v.y), "f"(v.z), "f"(v.w)
                     : "memory");
    }
}

// ---------------- pooling: fused tanh-attention softmax reduction ----------
// out = sum_h ( sum_n e^{tanh(x_n . attw_h)} * (x_n . dw_h) )
//             / ( sum_n e^{tanh(x_n . attw_h)} )  + b
// (tanh in [-1,1] -> exp safe without max-shift; ratio identical to reference)
__global__ void pool_kernel(const float* __restrict__ attw,
                            const float* __restrict__ dw) {
    __shared__ float sA[XDIM * HEADS];   // attw: [96,3] row-major
    __shared__ float sD[XDIM * HEADS];   // dense_w: [288] = [3][96] h-major
    int tid = threadIdx.x;
    for (int i = tid; i < XDIM * HEADS; i += blockDim.x) { sA[i] = attw[i]; sD[i] = dw[i]; }
    __syncthreads();

    int n = blockIdx.x * blockDim.x + tid;
    float sh[HEADS] = {0.f, 0.f, 0.f};
    float dh[HEADS] = {0.f, 0.f, 0.f};
    if (n < NN) {
        const float* x0 = g_out0 + (size_t)n * HF;
        const float* x1 = g_out1 + (size_t)n * HF;
        #pragma unroll 4
        for (int d = 0; d < XDIM; d++) {
            float xv = (d < HF) ? x0[d] : x1[d - HF];
            #pragma unroll
            for (int h = 0; h < HEADS; h++) {
                sh[h] += xv * sA[d * HEADS + h];
                dh[h] += xv * sD[h * XDIM + d];
            }
        }
    }
    float num[HEADS], den[HEADS];
    #pragma unroll
    for (int h = 0; h < HEADS; h++) {
        float w = (n < NN) ? __expf(tanhf(sh[h])) : 0.f;
        num[h] = w * dh[h];
        den[h] = w;
    }
    // warp reduction
    #pragma unroll
    for (int off = 16; off > 0; off >>= 1) {
        #pragma unroll
        for (int h = 0; h < HEADS; h++) {
            num[h] += __shfl_down_sync(0xFFFFFFFFu, num[h], off);
            den[h] += __shfl_down_sync(0xFFFFFFFFu, den[h], off);
        }
    }
    if ((tid & 31) == 0) {
        #pragma unroll
        for (int h = 0; h < HEADS; h++) {
            atomicAdd(&g_acc[h], num[h]);
            atomicAdd(&g_acc[HEADS + h], den[h]);
        }
    }
}

__global__ void finalize_kernel(const float* __restrict__ bias, float* __restrict__ out) {
    float r = 0.f;
    #pragma unroll
    for (int h = 0; h < HEADS; h++) r += g_acc[h] / g_acc[HEADS + h];
    out[0] = r + bias[0];
}

// ---------------------------------------------------------------------------
extern "C" void kernel_launch(void* const* d_in, const int* in_sizes, int n_in,
                              void* d_out, int out_size) {
    const float* node_feats = (const float*)d_in[0];
    const float* W_int   = (const float*)d_in[1];
    const float* asrc_i  = (const float*)d_in[2];
    const float* adst_i  = (const float*)d_in[3];
    const float* W_nh    = (const float*)d_in[4];
    const float* asrc_n  = (const float*)d_in[5];
    const float* adst_n  = (const float*)d_in[6];
    const float* att_w   = (const float*)d_in[7];
    const float* dense_w = (const float*)d_in[8];
    const float* dense_b = (const float*)d_in[9];
    const void*  edge_i  = d_in[10];
    const void*  edge_n  = d_in[11];
    float* out = (float*)d_out;

    // dtype detection + acc zero
    detect_kernel<<<1, 1>>>(edge_i, edge_n);

    // zero denominators and GAT output accumulators
    {
        int n1 = NN * HEADS;
        int n2 = NN * HF;
        zero_kernel<<<(n1 + 255) / 256, 256>>>(nullptr, 0); // no-op keep graph simple? (removed)
    }
    // (real zeroing below — explicit per-buffer)
    {
        int nden = NN * HEADS;
        int nout = NN * HF;
        float* pden0; cudaGetSymbolAddress((void**)&pden0, g_den0);
        float* pden1; cudaGetSymbolAddress((void**)&pden1, g_den1);
        float* pout0; cudaGetSymbolAddress((void**)&pout0, g_out0);
        float* pout1; cudaGetSymbolAddress((void**)&pout1, g_out1);
        zero_kernel<<<(nden + 255) / 256, 256>>>(pden0, nden);
        zero_kernel<<<(nden + 255) / 256, 256>>>(pden1, nden);
        zero_kernel<<<(nout + 255) / 256, 256>>>(pout0, nout);
        zero_kernel<<<(nout + 255) / 256, 256>>>(pout1, nout);
    }

    // node transform (both branches)
    node_kernel<<<(NN + 255) / 256, 256>>>(node_feats, W_int, asrc_i, adst_i,
                                           W_nh, asrc_n, adst_n);

    float* pes0; cudaGetSymbolAddress((void**)&pes0, g_es0);
    float* ped0; cudaGetSymbolAddress((void**)&ped0, g_ed0);
    float* pes1; cudaGetSymbolAddress((void**)&pes1, g_es1);
    float* ped1; cudaGetSymbolAddress((void**)&ped1, g_ed1);
    float* pden0; cudaGetSymbolAddress((void**)&pden0, g_den0);
    float* pden1; cudaGetSymbolAddress((void**)&pden1, g_den1);
    float* ph0;  cudaGetSymbolAddress((void**)&ph0, g_h0);
    float* ph1;  cudaGetSymbolAddress((void**)&ph1, g_h1);
    float* pout0; cudaGetSymbolAddress((void**)&pout0, g_out0);
    float* pout1; cudaGetSymbolAddress((void**)&pout1, g_out1);
    float* pp;   cudaGetSymbolAddress((void**)&pp, g_p);

    // branch int
    edge_pass1<<<(E_INT + 255) / 256, 256>>>(edge_i, E_INT, 0, pes0, ped0, pden0, pp);
    edge_pass2<<<(4 * E_INT + 255) / 256, 256>>>(edge_i, E_INT, 0, ph0, pden0, pp, pout0);

    // branch nh
    edge_pass1<<<(E_NH + 255) / 256, 256>>>(edge_n, E_NH, 1, pes1, ped1, pden1, pp);
    edge_pass2<<<(4 * E_NH + 255) / 256, 256>>>(edge_n, E_NH, 1, ph1, pden1, pp, pout1);

    // pooling reduction + finalize
    pool_kernel<<<(NN + 255) / 256, 256>>>(att_w, dense_w);
    finalize_kernel<<<1, 1>>>(dense_b, out);
}

// round 2
// speedup vs baseline: 1.4144x; 1.4144x over previous
#include <cuda_runtime.h>
#include <cuda_bf16.h>

// ---------------------------------------------------------------------------
// GNN15: two GAT branches (int: 400K edges, nh: 1.6M edges) over 100K nodes,
// HEADS=3, FILT=16, then global attention pooling to a scalar.
//
// R2: fused single edge pass per branch. Uses the identity
//   out[d] = (sum_e p_e * h[src_e]) / (den[d] + eps)
// so normalization happens per-node in the pooling kernel, not per-edge.
// Scores and denominators packed as float4 for vector loads / vector reds.
// ---------------------------------------------------------------------------

#define NN      100000
#define E_INT   400000
#define E_NH    1600000
#define VF      11
#define HEADS   3
#define HF      48      // HEADS*FILT
#define XDIM    96      // 2*HF

// ---------------- scratch (static device globals; no allocation) -----------
__device__ __align__(16) float g_h0[NN * HF];     // h for branch int
__device__ __align__(16) float g_h1[NN * HF];     // h for branch nh
__device__ __align__(16) float4 g_es4_0[NN];      // packed src scores (h0,h1,h2,0)
__device__ __align__(16) float4 g_ed4_0[NN];
__device__ __align__(16) float4 g_es4_1[NN];
__device__ __align__(16) float4 g_ed4_1[NN];
__device__ __align__(16) float4 g_den4_0[NN];     // softmax denominators
__device__ __align__(16) float4 g_den4_1[NN];
__device__ __align__(16) float g_out0[NN * HF];   // UNNORMALIZED sums
__device__ __align__(16) float g_out1[NN * HF];
__device__ float g_acc[8];                        // num[3], den[3]
__device__ int   g_is64[2];                       // edge dtype flags

// ---------------- init: zero scratch + detect edge dtype -------------------
// jax "int64" edges are int32 unless x64 is enabled. Values < 1e5 << 2^31,
// so if truly int64, every odd int32 word is 0. Check 16 of them.
__global__ void init_kernel(const void* e0, const void* e1) {
    size_t i = blockIdx.x * (size_t)blockDim.x + threadIdx.x;
    size_t stride = (size_t)gridDim.x * blockDim.x;
    float4 z4 = make_float4(0.f, 0.f, 0.f, 0.f);
    for (size_t k = i; k < NN; k += stride) { g_den4_0[k] = z4; g_den4_1[k] = z4; }
    float4* o0 = (float4*)g_out0;
    float4* o1 = (float4*)g_out1;
    for (size_t k = i; k < (size_t)NN * (HF / 4); k += stride) { o0[k] = z4; o1[k] = z4; }
    if (i == 0) {
        const int* a = (const int*)e0;
        const int* b = (const int*)e1;
        int is64a = 1, is64b = 1;
        #pragma unroll
        for (int t = 0; t < 16; t++) {
            if (a[2 * t + 1] != 0) is64a = 0;
            if (b[2 * t + 1] != 0) is64b = 0;
        }
        g_is64[0] = is64a;
        g_is64[1] = is64b;
        #pragma unroll
        for (int t = 0; t < 8; t++) g_acc[t] = 0.0f;
    }
}

// ---------------- node transform: h = x@W, packed es/ed scores -------------
__global__ void node_kernel(const float* __restrict__ feats,
                            const float* __restrict__ W0,
                            const float* __restrict__ as0, const float* __restrict__ ad0,
                            const float* __restrict__ W1,
                            const float* __restrict__ as1, const float* __restrict__ ad1) {
    __shared__ float sW[2][VF * HF];
    __shared__ float sAs[2][HF];
    __shared__ float sAd[2][HF];
    int tid = threadIdx.x;
    for (int i = tid; i < VF * HF; i += blockDim.x) { sW[0][i] = W0[i]; sW[1][i] = W1[i]; }
    for (int i = tid; i < HF; i += blockDim.x) {
        sAs[0][i] = as0[i]; sAd[0][i] = ad0[i];
        sAs[1][i] = as1[i]; sAd[1][i] = ad1[i];
    }
    __syncthreads();

    int n = blockIdx.x * blockDim.x + tid;
    if (n >= NN) return;

    float x[VF];
    #pragma unroll
    for (int k = 0; k < VF; k++) x[k] = feats[(size_t)n * VF + k];

    #pragma unroll
    for (int b = 0; b < 2; b++) {
        float* hout = (b == 0 ? g_h0 : g_h1) + (size_t)n * HF;
        float es[HEADS] = {0.f, 0.f, 0.f};
        float ed[HEADS] = {0.f, 0.f, 0.f};
        #pragma unroll
        for (int j = 0; j < HF; j++) {
            float s = 0.f;
            #pragma unroll
            for (int k = 0; k < VF; k++) s += x[k] * sW[b][k * HF + j];
            hout[j] = s;
            int hh = j >> 4;
            es[hh] += s * sAs[b][j];
            ed[hh] += s * sAd[b][j];
        }
        float4* pes = (b == 0 ? g_es4_0 : g_es4_1);
        float4* ped = (b == 0 ? g_ed4_0 : g_ed4_1);
        pes[n] = make_float4(es[0], es[1], es[2], 0.f);
        ped[n] = make_float4(ed[0], ed[1], ed[2], 0.f);
    }
}

// ---------------- fused edge pass: den += p ; out[dst] += p * h[src] -------
// 4 threads per edge. Every lane recomputes p (cheap: 1 broadcast float4
// load pair + 3 expf); lane 0 issues the denominator red.v4.
__global__ void __launch_bounds__(256) edge_fused(
        const void* __restrict__ edges, int E, int which,
        const float* __restrict__ hsrc,
        const float4* __restrict__ es4, const float4* __restrict__ ed4,
        float4* __restrict__ den4, float* __restrict__ out) {
    int t = blockIdx.x * blockDim.x + threadIdx.x;
    int e = t >> 2;
    int lane = t & 3;
    if (e >= E) return;
    int s, d;
    if (g_is64[which]) {
        const long long* E64 = (const long long*)edges;
        s = (int)E64[e]; d = (int)E64[E + e];
    } else {
        const int* E32 = (const int*)edges;
        s = E32[e]; d = E32[E + e];
    }
    float4 a = es4[s];
    float4 b = ed4[d];
    float v0 = a.x + b.x, v1 = a.y + b.y, v2 = a.z + b.z;
    v0 = v0 > 0.f ? v0 : 0.2f * v0;           // leaky_relu(0.2)
    v1 = v1 > 0.f ? v1 : 0.2f * v1;
    v2 = v2 > 0.f ? v2 : 0.2f * v2;
    float p0 = __expf(v0);                    // no max-shift needed (|v| small)
    float p1 = __expf(v1);
    float p2 = __expf(v2);

    if (lane == 0) {
        float* daddr = (float*)&den4[d];
        asm volatile("red.global.add.v4.f32 [%0], {%1,%2,%3,%4};"
                     :: "l"(daddr), "f"(p0), "f"(p1), "f"(p2), "f"(0.f)
                     : "memory");
    }

    const float4* hs = (const float4*)(hsrc + (size_t)s * HF);
    float* ob = out + (size_t)d * HF;
    float pk[3] = {p0, p1, p2};
    #pragma unroll
    for (int k = 0; k < HEADS; k++) {
        float4 v = hs[lane + 4 * k];
        float pp = pk[k];
        v.x *= pp; v.y *= pp; v.z *= pp; v.w *= pp;
        float* addr = ob + (size_t)(lane + 4 * k) * 4;
        asm volatile("red.global.add.v4.f32 [%0], {%1,%2,%3,%4};"
                     :: "l"(addr), "f"(v.x), "f"(v.y), "f"(v.z), "f"(v.w)
                     : "memory");
    }
}

// ---------------- pooling: normalize + fused tanh-attention reduction ------
// x_n[d] = out_raw[n][d] / (den[n][head(d)] + 1e-16)
// out = sum_h ( sum_n e^{tanh(x_n . attw_h)} * (x_n . dw_h) )
//             / ( sum_n e^{tanh(x_n . attw_h)} )  + b
__global__ void pool_kernel(const float* __restrict__ attw,
                            const float* __restrict__ dw) {
    __shared__ float sA[XDIM * HEADS];   // attw: [96,3] row-major
    __shared__ float sD[XDIM * HEADS];   // dense_w: [288] = [3][96] h-major
    int tid = threadIdx.x;
    for (int i = tid; i < XDIM * HEADS; i += blockDim.x) { sA[i] = attw[i]; sD[i] = dw[i]; }
    __syncthreads();

    int n = blockIdx.x * blockDim.x + tid;
    float sh[HEADS] = {0.f, 0.f, 0.f};
    float dh[HEADS] = {0.f, 0.f, 0.f};
    if (n < NN) {
        float4 dn0 = g_den4_0[n];
        float4 dn1 = g_den4_1[n];
        float inv0[HEADS] = {1.f / (dn0.x + 1e-16f), 1.f / (dn0.y + 1e-16f), 1.f / (dn0.z + 1e-16f)};
        float inv1[HEADS] = {1.f / (dn1.x + 1e-16f), 1.f / (dn1.y + 1e-16f), 1.f / (dn1.z + 1e-16f)};
        const float4* x0 = (const float4*)(g_out0 + (size_t)n * HF);
        const float4* x1 = (const float4*)(g_out1 + (size_t)n * HF);
        #pragma unroll
        for (int j = 0; j < HF / 4; j++) {
            float4 v0 = x0[j];
            float4 v1 = x1[j];
            int hh = j >> 2;           // head for this float4 (4 float4s per head)
            float q0[4] = {v0.x * inv0[hh], v0.y * inv0[hh], v0.z * inv0[hh], v0.w * inv0[hh]};
            float q1[4] = {v1.x * inv1[hh], v1.y * inv1[hh], v1.z * inv1[hh], v1.w * inv1[hh]};
            #pragma unroll
            for (int c = 0; c < 4; c++) {
                int d0 = j * 4 + c;        // dim in [0,48)
                int d1 = d0 + HF;          // dim in [48,96)
                #pragma unroll
                for (int h = 0; h < HEADS; h++) {
                    sh[h] += q0[c] * sA[d0 * HEADS + h] + q1[c] * sA[d1 * HEADS + h];
                    dh[h] += q0[c] * sD[h * XDIM + d0] + q1[c] * sD[h * XDIM + d1];
                }
            }
        }
    }
    float num[HEADS], den[HEADS];
    #pragma unroll
    for (int h = 0; h < HEADS; h++) {
        float w = (n < NN) ? __expf(tanhf(sh[h])) : 0.f;
        num[h] = w * dh[h];
        den[h] = w;
    }
    #pragma unroll
    for (int off = 16; off > 0; off >>= 1) {
        #pragma unroll
        for (int h = 0; h < HEADS; h++) {
            num[h] += __shfl_down_sync(0xFFFFFFFFu, num[h], off);
            den[h] += __shfl_down_sync(0xFFFFFFFFu, den[h], off);
        }
    }
    if ((tid & 31) == 0) {
        #pragma unroll
        for (int h = 0; h < HEADS; h++) {
            atomicAdd(&g_acc[h], num[h]);
            atomicAdd(&g_acc[HEADS + h], den[h]);
        }
    }
}

__global__ void finalize_kernel(const float* __restrict__ bias, float* __restrict__ out) {
    float r = 0.f;
    #pragma unroll
    for (int h = 0; h < HEADS; h++) r += g_acc[h] / g_acc[HEADS + h];
    out[0] = r + bias[0];
}

// ---------------------------------------------------------------------------
extern "C" void kernel_launch(void* const* d_in, const int* in_sizes, int n_in,
                              void* d_out, int out_size) {
    const float* node_feats = (const float*)d_in[0];
    const float* W_int   = (const float*)d_in[1];
    const float* asrc_i  = (const float*)d_in[2];
    const float* adst_i  = (const float*)d_in[3];
    const float* W_nh    = (const float*)d_in[4];
    const float* asrc_n  = (const float*)d_in[5];
    const float* adst_n  = (const float*)d_in[6];
    const float* att_w   = (const float*)d_in[7];
    const float* dense_w = (const float*)d_in[8];
    const float* dense_b = (const float*)d_in[9];
    const void*  edge_i  = d_in[10];
    const void*  edge_n  = d_in[11];
    float* out = (float*)d_out;

    init_kernel<<<2048, 256>>>(edge_i, edge_n);

    node_kernel<<<(NN + 255) / 256, 256>>>(node_feats, W_int, asrc_i, adst_i,
                                           W_nh, asrc_n, adst_n);

    float* ph0;   cudaGetSymbolAddress((void**)&ph0, g_h0);
    float* ph1;   cudaGetSymbolAddress((void**)&ph1, g_h1);
    float4* pes0; cudaGetSymbolAddress((void**)&pes0, g_es4_0);
    float4* ped0; cudaGetSymbolAddress((void**)&ped0, g_ed4_0);
    float4* pes1; cudaGetSymbolAddress((void**)&pes1, g_es4_1);
    float4* ped1; cudaGetSymbolAddress((void**)&ped1, g_ed4_1);
    float4* pden0; cudaGetSymbolAddress((void**)&pden0, g_den4_0);
    float4* pden1; cudaGetSymbolAddress((void**)&pden1, g_den4_1);
    float* pout0; cudaGetSymbolAddress((void**)&pout0, g_out0);
    float* pout1; cudaGetSymbolAddress((void**)&pout1, g_out1);

    edge_fused<<<(4 * E_INT + 255) / 256, 256>>>(edge_i, E_INT, 0, ph0, pes0, ped0, pden0, pout0);
    edge_fused<<<(4 * E_NH + 255) / 256, 256>>>(edge_n, E_NH, 1, ph1, pes1, ped1, pden1, pout1);

    pool_kernel<<<(NN + 255) / 256, 256>>>(att_w, dense_w);
    finalize_kernel<<<1, 1>>>(dense_b, out);
}